// round 10
// baseline (speedup 1.0000x reference)
#include <cuda_runtime.h>
#include <cuda_bf16.h>
#include <cstdint>

#define C 128
#define LDW 132
#define WSTR 136
#define WPL (64 * WSTR)
#define THREADS 1024
#define EPSF 1e-8f

__device__ float g_Mm[C * C];
__device__ float g_Md[C * C];
__device__ __align__(16) uint32_t g_BH[6][WPL];
__device__ __align__(16) uint32_t g_BL[6][WPL];

// ---- smem u32 layout ----
#define U_F0 16
#define U_F1 (U_F0 + 8448)
#define U_R2 (U_F1 + 8448)
#define U_R3 (U_R2 + 8448)
#define U_WH (U_R3 + 8448)
#define U_WL (U_WH + WPL)
#define U_RED (U_WL + WPL)   // red0[512], red1[512]
#define U_W0B (U_RED + 1024)
#define U_W1B (U_W0B + 64)
#define U_AB (U_W1B + 64)
#define U_BB (U_AB + 64)
#define U_W2 (U_BB + 64)
#define U_TOT (U_W2 + 128)

__device__ __forceinline__ uint32_t s2u(const void* p) {
    uint32_t a;
    asm("{ .reg .u64 t; cvta.to.shared.u64 t, %1; cvt.u32.u64 %0, t; }" : "=r"(a) : "l"(p));
    return a;
}
#define MBAR_INIT(a, c) asm volatile("mbarrier.init.shared.b64 [%0], %1;" ::"r"(a), "r"(c) : "memory")
#define MBAR_EXPECT(a, b) \
    asm volatile("mbarrier.arrive.expect_tx.shared.b64 _, [%0], %1;" ::"r"(a), "r"(b) : "memory")
__device__ __forceinline__ void mbar_wait(uint32_t a, uint32_t par) {
    asm volatile(
        "{\n\t.reg .pred P;\n\tWL_%=:\n\t"
        "mbarrier.try_wait.parity.acquire.cta.shared::cta.b64 P, [%0], %1, 0x989680;\n\t"
        "@P bra.uni WD_%=;\n\tbra.uni WL_%=;\n\tWD_%=:\n\t}" ::"r"(a), "r"(par) : "memory");
}
__device__ __forceinline__ void bulk_g2s(uint32_t dst, const void* gsrc, uint32_t bytes,
                                         uint32_t mbar) {
    asm volatile(
        "{ .reg .u64 g; cvta.to.global.u64 g, %1;\n\t"
        "cp.async.bulk.shared::cluster.global.mbarrier::complete_tx::bytes [%0], [g], %2, [%3]; }"
        ::"r"(dst), "l"(gsrc), "r"(bytes), "r"(mbar) : "memory");
}

__device__ __forceinline__ void split_pack(float x0, float x1, uint32_t& h, uint32_t& l) {
    uint32_t u0 = __float_as_uint(x0), u1 = __float_as_uint(x1);
    h = __byte_perm(u0, u1, 0x7632);
    float l0 = x0 - __uint_as_float(u0 & 0xFFFF0000u);
    float l1 = x1 - __uint_as_float(u1 & 0xFFFF0000u);
    __nv_bfloat162 t = __floats2bfloat162_rn(l0, l1);
    l = *(uint32_t*)&t;
}
__device__ __forceinline__ uint2 pack2(float x, float y) {
    uint2 r;
    split_pack(x, y, r.x, r.y);
    return r;
}
__device__ __forceinline__ float2 unpack2(uint2 p) {
    float2 a = __bfloat1622float2(*(__nv_bfloat162*)&p.x);
    float2 b = __bfloat1622float2(*(__nv_bfloat162*)&p.y);
    return make_float2(a.x + b.x, a.y + b.y);
}
__device__ __forceinline__ void mma16816(float* d, const uint32_t* a, uint32_t b0, uint32_t b1) {
    asm volatile(
        "mma.sync.aligned.m16n8k16.row.col.f32.bf16.bf16.f32 "
        "{%0,%1,%2,%3}, {%4,%5,%6,%7}, {%8,%9}, {%0,%1,%2,%3};"
        : "+f"(d[0]), "+f"(d[1]), "+f"(d[2]), "+f"(d[3])
        : "r"(a[0]), "r"(a[1]), "r"(a[2]), "r"(a[3]), "r"(b0), "r"(b1));
}
#define MMA3(accn, bh0, bh1, bl0, bl1) \
    do {                               \
        mma16816(accn, ah, bh0, bh1);  \
        mma16816(accn, al, bh0, bh1);  \
        mma16816(accn, ah, bl0, bl1);  \
    } while (0)

// 32 warps: rows rb..rb+15 (rb=(w&3)*16), cols cgrp*16..+15 (cgrp=w>>2).
// acc[nt][0..3]: rows (rb+g, rb+g+8), cols cgrp*16 + nt*8 + 2t (+1)
__device__ __forceinline__ void mma_block(const uint32_t* A, const uint32_t* WH,
                                          const uint32_t* WL, float acc[2][4], int rb, int c32,
                                          int ntb, int g, int t) {
    const uint32_t* pa = A + (rb + g) * LDW + 2 * t;
    const uint32_t* pb = WH + t * WSTR + c32 * 32 + g * 4 + ntb;
    const uint32_t* pc = WL + t * WSTR + c32 * 32 + g * 4 + ntb;
#pragma unroll 2
    for (int k0 = 0; k0 < 8; k0++) {
        uint2 a0 = *(const uint2*)pa, a1 = *(const uint2*)(pa + 8 * LDW);
        uint2 a2 = *(const uint2*)(pa + 8), a3 = *(const uint2*)(pa + 8 * LDW + 8);
        uint2 bh0 = *(const uint2*)pb, bh1 = *(const uint2*)(pb + 4 * WSTR);
        uint2 bl0 = *(const uint2*)pc, bl1 = *(const uint2*)(pc + 4 * WSTR);
        uint32_t ah[4] = {a0.x, a1.x, a2.x, a3.x}, al[4] = {a0.y, a1.y, a2.y, a3.y};
        MMA3(acc[0], bh0.x, bh1.x, bl0.x, bl1.x);
        MMA3(acc[1], bh0.y, bh1.y, bl0.y, bl1.y);
        pa += 16;
        pb += 8 * WSTR;
        pc += 8 * WSTR;
    }
}
__device__ __forceinline__ void mma_block2(const uint32_t* A0, const uint32_t* A1,
                                           const uint32_t* WH, const uint32_t* WL,
                                           float acc0[2][4], float acc1[2][4], int rb, int c32,
                                           int ntb, int g, int t) {
    const uint32_t* pa = A0 + (rb + g) * LDW + 2 * t;
    const uint32_t* pq = A1 + (rb + g) * LDW + 2 * t;
    const uint32_t* pb = WH + t * WSTR + c32 * 32 + g * 4 + ntb;
    const uint32_t* pc = WL + t * WSTR + c32 * 32 + g * 4 + ntb;
#pragma unroll 1
    for (int k0 = 0; k0 < 8; k0++) {
        uint2 bh0 = *(const uint2*)pb, bh1 = *(const uint2*)(pb + 4 * WSTR);
        uint2 bl0 = *(const uint2*)pc, bl1 = *(const uint2*)(pc + 4 * WSTR);
        {
            uint2 a0 = *(const uint2*)pa, a1 = *(const uint2*)(pa + 8 * LDW);
            uint2 a2 = *(const uint2*)(pa + 8), a3 = *(const uint2*)(pa + 8 * LDW + 8);
            uint32_t ah[4] = {a0.x, a1.x, a2.x, a3.x}, al[4] = {a0.y, a1.y, a2.y, a3.y};
            MMA3(acc0[0], bh0.x, bh1.x, bl0.x, bl1.x);
            MMA3(acc0[1], bh0.y, bh1.y, bl0.y, bl1.y);
        }
        {
            uint2 a0 = *(const uint2*)pq, a1 = *(const uint2*)(pq + 8 * LDW);
            uint2 a2 = *(const uint2*)(pq + 8), a3 = *(const uint2*)(pq + 8 * LDW + 8);
            uint32_t ah[4] = {a0.x, a1.x, a2.x, a3.x}, al[4] = {a0.y, a1.y, a2.y, a3.y};
            MMA3(acc1[0], bh0.x, bh1.x, bl0.x, bl1.x);
            MMA3(acc1[1], bh0.y, bh1.y, bl0.y, bl1.y);
        }
        pa += 16;
        pq += 16;
        pb += 8 * WSTR;
        pc += 8 * WSTR;
    }
}

// ---------------- prep ----------------
__global__ void precompute_M_kernel(const float* __restrict__ Wq_m, const float* __restrict__ Wk_m,
                                    const float* __restrict__ Wq_d, const float* __restrict__ Wk_d) {
    const float* Wq = blockIdx.y ? Wq_d : Wq_m;
    const float* Wk = blockIdx.y ? Wk_d : Wk_m;
    float* M = blockIdx.y ? g_Md : g_Mm;
    int i = blockIdx.x, t = threadIdx.x;
    __shared__ float qrow[C];
    qrow[t] = Wq[i * C + t];
    __syncthreads();
    const float* wkr = Wk + t * C;
    float a0 = 0.f, a1 = 0.f, a2 = 0.f, a3 = 0.f;
#pragma unroll 8
    for (int j = 0; j < C; j += 4) {
        a0 += qrow[j] * wkr[j];
        a1 += qrow[j + 1] * wkr[j + 1];
        a2 += qrow[j + 2] * wkr[j + 2];
        a3 += qrow[j + 3] * wkr[j + 3];
    }
    M[i * C + t] = ((a0 + a1) + (a2 + a3)) * 0.08838834764831845f;
}

__global__ void bake_kernel(const float* __restrict__ Wg, const float* __restrict__ Wvm,
                            const float* __restrict__ Wvd, const float* __restrict__ W1) {
    int w = blockIdx.y;
    const float* src = (w == 0) ? Wg : (w == 1) ? g_Mm : (w == 2) ? Wvm
                      : (w == 3) ? g_Md : (w == 4) ? Wvd : W1;
    int idx = blockIdx.x * blockDim.x + threadIdx.x;  // 0..8191
    int nt = idx & 3, g = (idx >> 2) & 7, c32 = (idx >> 5) & 3, k2 = idx >> 7;
    int n = c32 * 32 + nt * 8 + g;
    uint32_t h, l;
    split_pack(src[(2 * k2) * C + n], src[(2 * k2 + 1) * C + n], h, l);
    int dst = k2 * WSTR + (idx & 127);
    g_BH[w][dst] = h;
    g_BL[w][dst] = l;
}

// ---------------- fused ----------------
__global__ void __launch_bounds__(THREADS, 1)
fused_kernel(const float* __restrict__ em, const float* __restrict__ ed,
             const float* __restrict__ W2, float* __restrict__ out) {
    extern __shared__ uint32_t sm[];
    const uint32_t sb = s2u(sm);
    const uint32_t mb = sb;
    float* F0 = (float*)(sm + U_F0);
    float* F1 = (float*)(sm + U_F1);
    uint32_t* R2 = sm + U_R2;
    uint32_t* R3 = sm + U_R3;
    uint32_t* WH = sm + U_WH;
    uint32_t* WL = sm + U_WL;
    float* red0 = (float*)(sm + U_RED);
    float* red1 = red0 + 512;
    float* w0B = (float*)(sm + U_W0B);
    float* w1B = (float*)(sm + U_W1B);
    float* aB = (float*)(sm + U_AB);
    float* bB = (float*)(sm + U_BB);
    float* sW2 = (float*)(sm + U_W2);

    const int tid = threadIdx.x;
    const int w = tid >> 5, lane = tid & 31;
    const int g = lane >> 2, t = lane & 3;
    const int rb = (w & 3) * 16, cgrp = w >> 2;      // 8 col groups of 16
    const int c32 = cgrp >> 1, ntb = (cgrp & 1) * 2;
    const int r1 = rb + g, r2 = r1 + 8;
    const int cb = cgrp * 16 + 2 * t;  // col base (nt adds *8)
    const int row2 = w * 2;            // per-row epilogue mapping (2 rows/warp)
    const long base = (long)blockIdx.x * 64;

    if (tid == 0) {
        MBAR_INIT(mb, 1);
        MBAR_EXPECT(mb, 2 * WPL * 4);
        bulk_g2s(sb + U_WH * 4, &g_BH[0][0], WPL * 4, mb);
        bulk_g2s(sb + U_WL * 4, &g_BL[0][0], WPL * 4, mb);
    }
    {
        const float4* ge = (const float4*)(em + base * C);
        const float4* gd = (const float4*)(ed + base * C);
        for (int i = tid; i < 64 * 32; i += THREADS) {
            int r = i >> 5, c4 = i & 31;
            ((float4*)(F0 + r * LDW))[c4] = ge[i];
            ((float4*)(F1 + r * LDW))[c4] = gd[i];
        }
        if (tid < C) sW2[tid] = W2[tid];
    }
    __syncthreads();

    // adjacency scalars + pack em/ed (2 rows per warp)
#pragma unroll
    for (int rr = 0; rr < 2; rr++) {
        int r = row2 + rr;
        const float* pe = F0 + r * LDW;
        const float* pd = F1 + r * LDW;
        float2 e0 = *(const float2*)(pe + 2 * lane), e1 = *(const float2*)(pe + 2 * lane + 64);
        float2 d0 = *(const float2*)(pd + 2 * lane), d1 = *(const float2*)(pd + 2 * lane + 64);
        float sa = fabsf(e0.x - d0.x) + fabsf(e0.y - d0.y) + fabsf(e1.x - d1.x) + fabsf(e1.y - d1.y);
        float q0 = e0.x * e0.x + e0.y * e0.y + e1.x * e1.x + e1.y * e1.y;
        float q1 = d0.x * d0.x + d0.y * d0.y + d1.x * d1.x + d1.y * d1.y;
        float dp = e0.x * d0.x + e0.y * d0.y + e1.x * d1.x + e1.y * d1.y;
#pragma unroll
        for (int o = 16; o; o >>= 1) {
            sa += __shfl_xor_sync(~0u, sa, o);
            q0 += __shfl_xor_sync(~0u, q0, o);
            q1 += __shfl_xor_sync(~0u, q1, o);
            dp += __shfl_xor_sync(~0u, dp, o);
        }
        if (lane == 0) {
            float m = sa;
            float cosv = dp / (sqrtf(q0 + EPSF) * sqrtf(q1 + EPSF));
            float cp = cosv > 0.f ? cosv : 0.01f * cosv;
            aB[r] = fminf(1.f / (1.f + cp), 1.f / (1.f + m));
            bB[r] = fminf(cp / (1.f + cp), m / (1.f + m));
        }
        *(uint2*)(R2 + r * LDW + 2 * lane) = pack2(e0.x, e0.y);
        *(uint2*)(R2 + r * LDW + 2 * lane + 64) = pack2(e1.x, e1.y);
        *(uint2*)(R3 + r * LDW + 2 * lane) = pack2(d0.x, d0.y);
        *(uint2*)(R3 + r * LDW + 2 * lane + 64) = pack2(d1.x, d1.y);
    }
    __syncthreads();

    auto prefetch = [&](int nw) {
        if (tid == 0) {
            MBAR_EXPECT(mb, 2 * WPL * 4);
            bulk_g2s(sb + U_WH * 4, &g_BH[nw][0], WPL * 4, mb);
            bulk_g2s(sb + U_WL * 4, &g_BL[nw][0], WPL * 4, mb);
        }
    };

    // ---------------- stage 0: GCN ----------------
    mbar_wait(mb, 0);
    {
        float a0[2][4] = {}, a1[2][4] = {};
        mma_block2(R2, R3, WH, WL, a0, a1, rb, c32, ntb, g, t);
        __syncthreads();
        prefetch(1);
        float aa1 = aB[r1], bb1 = bB[r1], aa2 = aB[r2], bb2 = bB[r2];
#pragma unroll
        for (int nt = 0; nt < 2; nt++) {
            int c = cb + nt * 8;
            float2 e1v = *(const float2*)(F0 + r1 * LDW + c);
            float2 e2v = *(const float2*)(F0 + r2 * LDW + c);
            float2 d1v = *(const float2*)(F1 + r1 * LDW + c);
            float2 d2v = *(const float2*)(F1 + r2 * LDW + c);
            *(uint2*)(R2 + r1 * LDW + c) = pack2(fmaxf(aa1 * a0[nt][0] + bb1 * a1[nt][0], 0.f) + e1v.x,
                                                 fmaxf(aa1 * a0[nt][1] + bb1 * a1[nt][1], 0.f) + e1v.y);
            *(uint2*)(R2 + r2 * LDW + c) = pack2(fmaxf(aa2 * a0[nt][2] + bb2 * a1[nt][2], 0.f) + e2v.x,
                                                 fmaxf(aa2 * a0[nt][3] + bb2 * a1[nt][3], 0.f) + e2v.y);
            *(uint2*)(R3 + r1 * LDW + c) = pack2(fmaxf(bb1 * a0[nt][0] + aa1 * a1[nt][0], 0.f) + d1v.x,
                                                 fmaxf(bb1 * a0[nt][1] + aa1 * a1[nt][1], 0.f) + d1v.y);
            *(uint2*)(R3 + r2 * LDW + c) = pack2(fmaxf(bb2 * a0[nt][2] + aa2 * a1[nt][2], 0.f) + d2v.x,
                                                 fmaxf(bb2 * a0[nt][3] + aa2 * a1[nt][3], 0.f) + d2v.y);
        }
    }
    __syncthreads();

    // T-stage with folded scores + u-pack
    auto t_stage = [&](const float* F, uint32_t* X, int par, int nw) {
        mbar_wait(mb, par);
        float acc[2][4] = {};
        mma_block(X, WH, WL, acc, rb, c32, ntb, g, t);
        __syncthreads();
        prefetch(nw);
        float s0a = 0.f, s1a = 0.f, s0b = 0.f, s1b = 0.f;
#pragma unroll
        for (int nt = 0; nt < 2; nt++) {
            int c = cb + nt * 8;
            float2 f1v = *(const float2*)(F + r1 * LDW + c);
            float2 f2v = *(const float2*)(F + r2 * LDW + c);
            float2 x1v = unpack2(*(const uint2*)(X + r1 * LDW + c));
            float2 x2v = unpack2(*(const uint2*)(X + r2 * LDW + c));
            s0a += acc[nt][0] * f1v.x + acc[nt][1] * f1v.y;
            s1a += acc[nt][0] * x1v.x + acc[nt][1] * x1v.y;
            s0b += acc[nt][2] * f2v.x + acc[nt][3] * f2v.y;
            s1b += acc[nt][2] * x2v.x + acc[nt][3] * x2v.y;
        }
#pragma unroll
        for (int o = 1; o < 4; o <<= 1) {
            s0a += __shfl_xor_sync(~0u, s0a, o);
            s1a += __shfl_xor_sync(~0u, s1a, o);
            s0b += __shfl_xor_sync(~0u, s0b, o);
            s1b += __shfl_xor_sync(~0u, s1b, o);
        }
        if (t == 0) {
            red0[cgrp * 64 + r1] = s0a;
            red1[cgrp * 64 + r1] = s1a;
            red0[cgrp * 64 + r2] = s0b;
            red1[cgrp * 64 + r2] = s1b;
        }
        __syncthreads();
        if (tid < 64) {
            float S0 = 0.f, S1 = 0.f;
#pragma unroll
            for (int cc = 0; cc < 8; cc++) {
                S0 += red0[cc * 64 + tid];
                S1 += red1[cc * 64 + tid];
            }
            float mx = fmaxf(S0, S1);
            float e0 = expf(S0 - mx), e1 = expf(S1 - mx);
            float inv = 1.f / (e0 + e1);
            w0B[tid] = e0 * inv;
            w1B[tid] = e1 * inv;
        }
        __syncthreads();
#pragma unroll
        for (int rr = 0; rr < 2; rr++) {
            int r = row2 + rr;
            float w0 = w0B[r], w1 = w1B[r];
            float2 f0v = *(const float2*)(F + r * LDW + 2 * lane);
            float2 f1v = *(const float2*)(F + r * LDW + 2 * lane + 64);
            float2 x0v = unpack2(*(const uint2*)(X + r * LDW + 2 * lane));
            float2 x1v = unpack2(*(const uint2*)(X + r * LDW + 2 * lane + 64));
            *(uint2*)(X + r * LDW + 2 * lane) = pack2(w0 * f0v.x + w1 * x0v.x, w0 * f0v.y + w1 * x0v.y);
            *(uint2*)(X + r * LDW + 2 * lane + 64) =
                pack2(w0 * f1v.x + w1 * x1v.x, w0 * f1v.y + w1 * x1v.y);
        }
        __syncthreads();
    };

    // ---------------- m branch ----------------
    t_stage(F0, R2, 1, 2);  // u_m -> R2
    mbar_wait(mb, 0);       // Wvm
    {
        float acc[2][4] = {};
        mma_block(R2, WH, WL, acc, rb, c32, ntb, g, t);
        __syncthreads();
        prefetch(3);
#pragma unroll
        for (int nt = 0; nt < 2; nt++) {  // mLA -> F0
            int c = cb + nt * 8;
            *(float2*)(F0 + r1 * LDW + c) = make_float2(acc[nt][0], acc[nt][1]);
            *(float2*)(F0 + r2 * LDW + c) = make_float2(acc[nt][2], acc[nt][3]);
        }
    }
    __syncthreads();

    // ---------------- d branch ----------------
    t_stage(F1, R3, 1, 4);  // u_d -> R3
    mbar_wait(mb, 0);       // Wvd
    {
        float acc[2][4] = {};
        mma_block(R3, WH, WL, acc, rb, c32, ntb, g, t);
        __syncthreads();
        prefetch(5);
#pragma unroll
        for (int nt = 0; nt < 2; nt++) {  // ne = mLA * dLA -> R2 packed
            int c = cb + nt * 8;
            float2 m1v = *(const float2*)(F0 + r1 * LDW + c);
            float2 m2v = *(const float2*)(F0 + r2 * LDW + c);
            *(uint2*)(R2 + r1 * LDW + c) = pack2(acc[nt][0] * m1v.x, acc[nt][1] * m1v.y);
            *(uint2*)(R2 + r2 * LDW + c) = pack2(acc[nt][2] * m2v.x, acc[nt][3] * m2v.y);
        }
    }
    __syncthreads();

    // ---------------- head ----------------
    mbar_wait(mb, 1);  // W1
    {
        float acc[2][4] = {};
        mma_block(R2, WH, WL, acc, rb, c32, ntb, g, t);
        float pa = 0.f, pb = 0.f;
#pragma unroll
        for (int nt = 0; nt < 2; nt++) {
            int c = cb + nt * 8;
            float2 wv = *(const float2*)(sW2 + c);
            pa += fmaxf(acc[nt][0], 0.f) * wv.x + fmaxf(acc[nt][1], 0.f) * wv.y;
            pb += fmaxf(acc[nt][2], 0.f) * wv.x + fmaxf(acc[nt][3], 0.f) * wv.y;
        }
#pragma unroll
        for (int o = 1; o < 4; o <<= 1) {
            pa += __shfl_xor_sync(~0u, pa, o);
            pb += __shfl_xor_sync(~0u, pb, o);
        }
        __syncthreads();
        if (t == 0) {
            red0[cgrp * 64 + r1] = pa;
            red0[cgrp * 64 + r2] = pb;
        }
        __syncthreads();
        if (tid < 64) {
            float P = 0.f;
#pragma unroll
            for (int cc = 0; cc < 8; cc++) P += red0[cc * 64 + tid];
            out[base + tid] = 1.f / (1.f + expf(-P));
        }
    }
}

// ---------------------------------------------------------------------------
extern "C" void kernel_launch(void* const* d_in, const int* in_sizes, int n_in,
                              void* d_out, int out_size) {
    const float* em    = (const float*)d_in[0];
    const float* ed    = (const float*)d_in[1];
    const float* W_gcn = (const float*)d_in[2];
    const float* Wq_m  = (const float*)d_in[3];
    const float* Wk_m  = (const float*)d_in[4];
    const float* Wv_m  = (const float*)d_in[5];
    const float* Wq_d  = (const float*)d_in[6];
    const float* Wk_d  = (const float*)d_in[7];
    const float* Wv_d  = (const float*)d_in[8];
    const float* W1    = (const float*)d_in[9];
    const float* W2    = (const float*)d_in[10];
    float* out = (float*)d_out;

    const int B = in_sizes[0] / C;
    const int smem_bytes = U_TOT * 4;

    precompute_M_kernel<<<dim3(C, 2), C>>>(Wq_m, Wk_m, Wq_d, Wk_d);
    bake_kernel<<<dim3(8192 / 256, 6), 256>>>(W_gcn, Wv_m, Wv_d, W1);

    cudaFuncSetAttribute(fused_kernel,
                         cudaFuncAttributeMaxDynamicSharedMemorySize, smem_bytes);
    fused_kernel<<<B / 64, THREADS, smem_bytes>>>(em, ed, W2, out);
}

// round 11
// speedup vs baseline: 1.2408x; 1.2408x over previous
#include <cuda_runtime.h>
#include <cuda_bf16.h>
#include <cstdint>

#define C 128
#define LDW 132
#define WSTR 136
#define WPL (64 * WSTR)
#define THREADS 512
#define EPSF 1e-8f

__device__ float g_Mm[C * C];
__device__ float g_Md[C * C];
__device__ __align__(16) uint32_t g_BH[6][WPL];
__device__ __align__(16) uint32_t g_BL[6][WPL];

// ---- smem u32 layout ----
#define U_F0 16
#define U_F1 (U_F0 + 8448)
#define U_R2 (U_F1 + 8448)
#define U_R3 (U_R2 + 8448)
#define U_WH (U_R3 + 8448)
#define U_WL (U_WH + WPL)
#define U_RED (U_WL + WPL)   // red0[256], red1[256]
#define U_W0B (U_RED + 512)
#define U_W1B (U_W0B + 64)
#define U_AB (U_W1B + 64)
#define U_BB (U_AB + 64)
#define U_W2 (U_BB + 64)
#define U_TOT (U_W2 + 128)

__device__ __forceinline__ uint32_t s2u(const void* p) {
    uint32_t a;
    asm("{ .reg .u64 t; cvta.to.shared.u64 t, %1; cvt.u32.u64 %0, t; }" : "=r"(a) : "l"(p));
    return a;
}
#define MBAR_INIT(a, c) asm volatile("mbarrier.init.shared.b64 [%0], %1;" ::"r"(a), "r"(c) : "memory")
#define MBAR_EXPECT(a, b) \
    asm volatile("mbarrier.arrive.expect_tx.shared.b64 _, [%0], %1;" ::"r"(a), "r"(b) : "memory")
__device__ __forceinline__ void mbar_wait(uint32_t a, uint32_t par) {
    asm volatile(
        "{\n\t.reg .pred P;\n\tWL_%=:\n\t"
        "mbarrier.try_wait.parity.acquire.cta.shared::cta.b64 P, [%0], %1, 0x989680;\n\t"
        "@P bra.uni WD_%=;\n\tbra.uni WL_%=;\n\tWD_%=:\n\t}" ::"r"(a), "r"(par) : "memory");
}
__device__ __forceinline__ void bulk_g2s(uint32_t dst, const void* gsrc, uint32_t bytes,
                                         uint32_t mbar) {
    asm volatile(
        "{ .reg .u64 g; cvta.to.global.u64 g, %1;\n\t"
        "cp.async.bulk.shared::cluster.global.mbarrier::complete_tx::bytes [%0], [g], %2, [%3]; }"
        ::"r"(dst), "l"(gsrc), "r"(bytes), "r"(mbar) : "memory");
}

__device__ __forceinline__ void split_pack(float x0, float x1, uint32_t& h, uint32_t& l) {
    uint32_t u0 = __float_as_uint(x0), u1 = __float_as_uint(x1);
    h = __byte_perm(u0, u1, 0x7632);
    float l0 = x0 - __uint_as_float(u0 & 0xFFFF0000u);
    float l1 = x1 - __uint_as_float(u1 & 0xFFFF0000u);
    __nv_bfloat162 t = __floats2bfloat162_rn(l0, l1);
    l = *(uint32_t*)&t;
}
__device__ __forceinline__ uint2 pack2(float x, float y) {
    uint2 r;
    split_pack(x, y, r.x, r.y);
    return r;
}
__device__ __forceinline__ float2 unpack2(uint2 p) {
    float2 a = __bfloat1622float2(*(__nv_bfloat162*)&p.x);
    float2 b = __bfloat1622float2(*(__nv_bfloat162*)&p.y);
    return make_float2(a.x + b.x, a.y + b.y);
}
__device__ __forceinline__ void mma16816(float* d, const uint32_t* a, uint32_t b0, uint32_t b1) {
    asm volatile(
        "mma.sync.aligned.m16n8k16.row.col.f32.bf16.bf16.f32 "
        "{%0,%1,%2,%3}, {%4,%5,%6,%7}, {%8,%9}, {%0,%1,%2,%3};"
        : "+f"(d[0]), "+f"(d[1]), "+f"(d[2]), "+f"(d[3])
        : "r"(a[0]), "r"(a[1]), "r"(a[2]), "r"(a[3]), "r"(b0), "r"(b1));
}

// ---- hi-phase: acc += Ah@Bh + Al@Bh (16 warps: rows (w&3)*16, cols (w>>2)*32)
__device__ __forceinline__ void mma_blockH(const uint32_t* A, const uint32_t* WH, float acc[4][4],
                                           int rb, int c32, int g, int t) {
    const uint32_t* pa = A + (rb + g) * LDW + 2 * t;
    const uint32_t* pb = WH + t * WSTR + c32 * 32 + g * 4;
#pragma unroll 2
    for (int k0 = 0; k0 < 8; k0++) {
        uint2 a0 = *(const uint2*)pa, a1 = *(const uint2*)(pa + 8 * LDW);
        uint2 a2 = *(const uint2*)(pa + 8), a3 = *(const uint2*)(pa + 8 * LDW + 8);
        uint4 b0 = *(const uint4*)pb, b1 = *(const uint4*)(pb + 4 * WSTR);
        uint32_t ah[4] = {a0.x, a1.x, a2.x, a3.x}, al[4] = {a0.y, a1.y, a2.y, a3.y};
        mma16816(acc[0], ah, b0.x, b1.x); mma16816(acc[0], al, b0.x, b1.x);
        mma16816(acc[1], ah, b0.y, b1.y); mma16816(acc[1], al, b0.y, b1.y);
        mma16816(acc[2], ah, b0.z, b1.z); mma16816(acc[2], al, b0.z, b1.z);
        mma16816(acc[3], ah, b0.w, b1.w); mma16816(acc[3], al, b0.w, b1.w);
        pa += 16;
        pb += 8 * WSTR;
    }
}
// ---- lo-phase: acc += Ah@Bl
__device__ __forceinline__ void mma_blockL(const uint32_t* A, const uint32_t* WL, float acc[4][4],
                                           int rb, int c32, int g, int t) {
    const uint32_t* pa = A + (rb + g) * LDW + 2 * t;
    const uint32_t* pc = WL + t * WSTR + c32 * 32 + g * 4;
#pragma unroll 2
    for (int k0 = 0; k0 < 8; k0++) {
        uint2 a0 = *(const uint2*)pa, a1 = *(const uint2*)(pa + 8 * LDW);
        uint2 a2 = *(const uint2*)(pa + 8), a3 = *(const uint2*)(pa + 8 * LDW + 8);
        uint4 b0 = *(const uint4*)pc, b1 = *(const uint4*)(pc + 4 * WSTR);
        uint32_t ah[4] = {a0.x, a1.x, a2.x, a3.x};
        mma16816(acc[0], ah, b0.x, b1.x);
        mma16816(acc[1], ah, b0.y, b1.y);
        mma16816(acc[2], ah, b0.z, b1.z);
        mma16816(acc[3], ah, b0.w, b1.w);
        pa += 16;
        pc += 8 * WSTR;
    }
}

// ---------------- prep ----------------
__global__ void precompute_M_kernel(const float* __restrict__ Wq_m, const float* __restrict__ Wk_m,
                                    const float* __restrict__ Wq_d, const float* __restrict__ Wk_d) {
    const float* Wq = blockIdx.y ? Wq_d : Wq_m;
    const float* Wk = blockIdx.y ? Wk_d : Wk_m;
    float* M = blockIdx.y ? g_Md : g_Mm;
    int i = blockIdx.x, t = threadIdx.x;
    __shared__ float qrow[C];
    qrow[t] = Wq[i * C + t];
    __syncthreads();
    const float* wkr = Wk + t * C;
    float a0 = 0.f, a1 = 0.f, a2 = 0.f, a3 = 0.f;
#pragma unroll 8
    for (int j = 0; j < C; j += 4) {
        a0 += qrow[j] * wkr[j];
        a1 += qrow[j + 1] * wkr[j + 1];
        a2 += qrow[j + 2] * wkr[j + 2];
        a3 += qrow[j + 3] * wkr[j + 3];
    }
    M[i * C + t] = ((a0 + a1) + (a2 + a3)) * 0.08838834764831845f;
}

__global__ void bake_kernel(const float* __restrict__ Wg, const float* __restrict__ Wvm,
                            const float* __restrict__ Wvd, const float* __restrict__ W1) {
    int w = blockIdx.y;
    const float* src = (w == 0) ? Wg : (w == 1) ? g_Mm : (w == 2) ? Wvm
                      : (w == 3) ? g_Md : (w == 4) ? Wvd : W1;
    int idx = blockIdx.x * blockDim.x + threadIdx.x;  // 0..8191
    int nt = idx & 3, g = (idx >> 2) & 7, c32 = (idx >> 5) & 3, k2 = idx >> 7;
    int n = c32 * 32 + nt * 8 + g;
    uint32_t h, l;
    split_pack(src[(2 * k2) * C + n], src[(2 * k2 + 1) * C + n], h, l);
    int dst = k2 * WSTR + (idx & 127);
    g_BH[w][dst] = h;
    g_BL[w][dst] = l;
}

// ---------------- fused ----------------
__global__ void __launch_bounds__(THREADS, 1)
fused_kernel(const float* __restrict__ em, const float* __restrict__ ed,
             const float* __restrict__ W2, float* __restrict__ out) {
    extern __shared__ uint32_t sm[];
    const uint32_t sb = s2u(sm);
    const uint32_t mbH = sb, mbL = sb + 8;
    float* F0 = (float*)(sm + U_F0);
    float* F1 = (float*)(sm + U_F1);
    uint32_t* R2 = sm + U_R2;
    uint32_t* R3 = sm + U_R3;
    uint32_t* WH = sm + U_WH;
    uint32_t* WL = sm + U_WL;
    float* red0 = (float*)(sm + U_RED);
    float* red1 = red0 + 256;
    float* w0B = (float*)(sm + U_W0B);
    float* w1B = (float*)(sm + U_W1B);
    float* aB = (float*)(sm + U_AB);
    float* bB = (float*)(sm + U_BB);
    float* sW2 = (float*)(sm + U_W2);

    const int tid = threadIdx.x;
    const int w = tid >> 5, lane = tid & 31;
    const int g = lane >> 2, t = lane & 3;
    const int rb = (w & 3) * 16, c32 = w >> 2;
    const int r1 = rb + g, r2 = r1 + 8;
    const int cb = c32 * 32 + 2 * t;
    const int row4 = w * 4;
    const long base = (long)blockIdx.x * 64;

    if (tid == 0) {
        MBAR_INIT(mbH, 1);
        MBAR_INIT(mbL, 1);
        MBAR_EXPECT(mbH, WPL * 4);
        bulk_g2s(sb + U_WH * 4, &g_BH[0][0], WPL * 4, mbH);
        MBAR_EXPECT(mbL, WPL * 4);
        bulk_g2s(sb + U_WL * 4, &g_BL[0][0], WPL * 4, mbL);
    }
    {
        const float4* ge = (const float4*)(em + base * C);
        const float4* gd = (const float4*)(ed + base * C);
        for (int i = tid; i < 64 * 32; i += THREADS) {
            int r = i >> 5, c4 = i & 31;
            ((float4*)(F0 + r * LDW))[c4] = ge[i];
            ((float4*)(F1 + r * LDW))[c4] = gd[i];
        }
        if (tid < C) sW2[tid] = W2[tid];
    }
    __syncthreads();

    // adjacency scalars + pack em/ed
#pragma unroll
    for (int rr = 0; rr < 4; rr++) {
        int r = row4 + rr;
        const float* pe = F0 + r * LDW;
        const float* pd = F1 + r * LDW;
        float2 e0 = *(const float2*)(pe + 2 * lane), e1 = *(const float2*)(pe + 2 * lane + 64);
        float2 d0 = *(const float2*)(pd + 2 * lane), d1 = *(const float2*)(pd + 2 * lane + 64);
        float sa = fabsf(e0.x - d0.x) + fabsf(e0.y - d0.y) + fabsf(e1.x - d1.x) + fabsf(e1.y - d1.y);
        float q0 = e0.x * e0.x + e0.y * e0.y + e1.x * e1.x + e1.y * e1.y;
        float q1 = d0.x * d0.x + d0.y * d0.y + d1.x * d1.x + d1.y * d1.y;
        float dp = e0.x * d0.x + e0.y * d0.y + e1.x * d1.x + e1.y * d1.y;
#pragma unroll
        for (int o = 16; o; o >>= 1) {
            sa += __shfl_xor_sync(~0u, sa, o);
            q0 += __shfl_xor_sync(~0u, q0, o);
            q1 += __shfl_xor_sync(~0u, q1, o);
            dp += __shfl_xor_sync(~0u, dp, o);
        }
        if (lane == 0) {
            float m = sa;
            float cosv = dp / (sqrtf(q0 + EPSF) * sqrtf(q1 + EPSF));
            float cp = cosv > 0.f ? cosv : 0.01f * cosv;
            aB[r] = fminf(1.f / (1.f + cp), 1.f / (1.f + m));
            bB[r] = fminf(cp / (1.f + cp), m / (1.f + m));
        }
        *(uint2*)(R2 + r * LDW + 2 * lane) = pack2(e0.x, e0.y);
        *(uint2*)(R2 + r * LDW + 2 * lane + 64) = pack2(e1.x, e1.y);
        *(uint2*)(R3 + r * LDW + 2 * lane) = pack2(d0.x, d0.y);
        *(uint2*)(R3 + r * LDW + 2 * lane + 64) = pack2(d1.x, d1.y);
    }
    __syncthreads();

    auto prefH = [&](int nw) {
        if (tid == 0) {
            MBAR_EXPECT(mbH, WPL * 4);
            bulk_g2s(sb + U_WH * 4, &g_BH[nw][0], WPL * 4, mbH);
        }
    };
    auto prefL = [&](int nw) {
        if (tid == 0) {
            MBAR_EXPECT(mbL, WPL * 4);
            bulk_g2s(sb + U_WL * 4, &g_BL[nw][0], WPL * 4, mbL);
        }
    };

    // ---------------- stage 0: GCN (sp=0) ----------------
    {
        float a0[4][4] = {}, a1[4][4] = {};
        mbar_wait(mbH, 0);
        mma_blockH(R2, WH, a0, rb, c32, g, t);
        mma_blockH(R3, WH, a1, rb, c32, g, t);
        __syncthreads();  // WH free
        prefH(1);
        mbar_wait(mbL, 0);
        mma_blockL(R2, WL, a0, rb, c32, g, t);
        mma_blockL(R3, WL, a1, rb, c32, g, t);
        __syncthreads();  // WL free + A reads done
        prefL(1);
        float aa1 = aB[r1], bb1 = bB[r1], aa2 = aB[r2], bb2 = bB[r2];
#pragma unroll
        for (int nt = 0; nt < 4; nt++) {
            int c = cb + nt * 8;
            float2 e1v = *(const float2*)(F0 + r1 * LDW + c);
            float2 e2v = *(const float2*)(F0 + r2 * LDW + c);
            float2 d1v = *(const float2*)(F1 + r1 * LDW + c);
            float2 d2v = *(const float2*)(F1 + r2 * LDW + c);
            *(uint2*)(R2 + r1 * LDW + c) = pack2(fmaxf(aa1 * a0[nt][0] + bb1 * a1[nt][0], 0.f) + e1v.x,
                                                 fmaxf(aa1 * a0[nt][1] + bb1 * a1[nt][1], 0.f) + e1v.y);
            *(uint2*)(R2 + r2 * LDW + c) = pack2(fmaxf(aa2 * a0[nt][2] + bb2 * a1[nt][2], 0.f) + e2v.x,
                                                 fmaxf(aa2 * a0[nt][3] + bb2 * a1[nt][3], 0.f) + e2v.y);
            *(uint2*)(R3 + r1 * LDW + c) = pack2(fmaxf(bb1 * a0[nt][0] + aa1 * a1[nt][0], 0.f) + d1v.x,
                                                 fmaxf(bb1 * a0[nt][1] + aa1 * a1[nt][1], 0.f) + d1v.y);
            *(uint2*)(R3 + r2 * LDW + c) = pack2(fmaxf(bb2 * a0[nt][2] + aa2 * a1[nt][2], 0.f) + d2v.x,
                                                 fmaxf(bb2 * a0[nt][3] + aa2 * a1[nt][3], 0.f) + d2v.y);
        }
    }
    __syncthreads();

    // generic pipelined GEMM: acc = X @ W(stage sp), with prefetches
    auto gemm_stage = [&](const uint32_t* X, float acc[4][4], int sp, int nwH, int nwL) {
        mbar_wait(mbH, sp);
        mma_blockH(X, WH, acc, rb, c32, g, t);
        __syncthreads();
        if (nwH >= 0) prefH(nwH);
        mbar_wait(mbL, sp);
        mma_blockL(X, WL, acc, rb, c32, g, t);
        __syncthreads();
        if (nwL >= 0) prefL(nwL);
    };

    // T-stage epilogue: folded scores + softmax + u-pack (u overwrites X)
    auto score_u = [&](const float* F, uint32_t* X, const float acc[4][4]) {
        float s0a = 0.f, s1a = 0.f, s0b = 0.f, s1b = 0.f;
#pragma unroll
        for (int nt = 0; nt < 4; nt++) {
            int c = cb + nt * 8;
            float2 f1v = *(const float2*)(F + r1 * LDW + c);
            float2 f2v = *(const float2*)(F + r2 * LDW + c);
            float2 x1v = unpack2(*(const uint2*)(X + r1 * LDW + c));
            float2 x2v = unpack2(*(const uint2*)(X + r2 * LDW + c));
            s0a += acc[nt][0] * f1v.x + acc[nt][1] * f1v.y;
            s1a += acc[nt][0] * x1v.x + acc[nt][1] * x1v.y;
            s0b += acc[nt][2] * f2v.x + acc[nt][3] * f2v.y;
            s1b += acc[nt][2] * x2v.x + acc[nt][3] * x2v.y;
        }
#pragma unroll
        for (int o = 1; o < 4; o <<= 1) {
            s0a += __shfl_xor_sync(~0u, s0a, o);
            s1a += __shfl_xor_sync(~0u, s1a, o);
            s0b += __shfl_xor_sync(~0u, s0b, o);
            s1b += __shfl_xor_sync(~0u, s1b, o);
        }
        if (t == 0) {
            red0[c32 * 64 + r1] = s0a;
            red1[c32 * 64 + r1] = s1a;
            red0[c32 * 64 + r2] = s0b;
            red1[c32 * 64 + r2] = s1b;
        }
        __syncthreads();
        if (tid < 64) {
            float S0 = red0[tid] + red0[64 + tid] + red0[128 + tid] + red0[192 + tid];
            float S1 = red1[tid] + red1[64 + tid] + red1[128 + tid] + red1[192 + tid];
            float mx = fmaxf(S0, S1);
            float e0 = expf(S0 - mx), e1 = expf(S1 - mx);
            float inv = 1.f / (e0 + e1);
            w0B[tid] = e0 * inv;
            w1B[tid] = e1 * inv;
        }
        __syncthreads();
#pragma unroll
        for (int rr = 0; rr < 4; rr++) {
            int r = row4 + rr;
            float w0 = w0B[r], w1 = w1B[r];
            float2 f0v = *(const float2*)(F + r * LDW + 2 * lane);
            float2 f1v = *(const float2*)(F + r * LDW + 2 * lane + 64);
            float2 x0v = unpack2(*(const uint2*)(X + r * LDW + 2 * lane));
            float2 x1v = unpack2(*(const uint2*)(X + r * LDW + 2 * lane + 64));
            *(uint2*)(X + r * LDW + 2 * lane) = pack2(w0 * f0v.x + w1 * x0v.x, w0 * f0v.y + w1 * x0v.y);
            *(uint2*)(X + r * LDW + 2 * lane + 64) =
                pack2(w0 * f1v.x + w1 * x1v.x, w0 * f1v.y + w1 * x1v.y);
        }
        __syncthreads();
    };

    // ---------------- m branch ----------------
    {   // stage 1: T_m (Mm), sp=1
        float acc[4][4] = {};
        gemm_stage(R2, acc, 1, 2, 2);
        score_u(F0, R2, acc);
    }
    {   // stage 2: mLA (Wvm), sp=0
        float acc[4][4] = {};
        gemm_stage(R2, acc, 0, 3, 3);
#pragma unroll
        for (int nt = 0; nt < 4; nt++) {
            int c = cb + nt * 8;
            *(float2*)(F0 + r1 * LDW + c) = make_float2(acc[nt][0], acc[nt][1]);
            *(float2*)(F0 + r2 * LDW + c) = make_float2(acc[nt][2], acc[nt][3]);
        }
        __syncthreads();
    }

    // ---------------- d branch ----------------
    {   // stage 3: T_d (Md), sp=1
        float acc[4][4] = {};
        gemm_stage(R3, acc, 1, 4, 4);
        score_u(F1, R3, acc);
    }
    {   // stage 4: dLA (Wvd), sp=0; ne = mLA*dLA -> R2 packed
        float acc[4][4] = {};
        gemm_stage(R3, acc, 0, 5, 5);
#pragma unroll
        for (int nt = 0; nt < 4; nt++) {
            int c = cb + nt * 8;
            float2 m1v = *(const float2*)(F0 + r1 * LDW + c);
            float2 m2v = *(const float2*)(F0 + r2 * LDW + c);
            *(uint2*)(R2 + r1 * LDW + c) = pack2(acc[nt][0] * m1v.x, acc[nt][1] * m1v.y);
            *(uint2*)(R2 + r2 * LDW + c) = pack2(acc[nt][2] * m2v.x, acc[nt][3] * m2v.y);
        }
        __syncthreads();
    }

    // ---------------- head: stage 5 (W1), sp=1 ----------------
    {
        float acc[4][4] = {};
        gemm_stage(R2, acc, 1, -1, -1);
        float pa = 0.f, pb = 0.f;
#pragma unroll
        for (int nt = 0; nt < 4; nt++) {
            int c = cb + nt * 8;
            float2 wv = *(const float2*)(sW2 + c);
            pa += fmaxf(acc[nt][0], 0.f) * wv.x + fmaxf(acc[nt][1], 0.f) * wv.y;
            pb += fmaxf(acc[nt][2], 0.f) * wv.x + fmaxf(acc[nt][3], 0.f) * wv.y;
        }
#pragma unroll
        for (int o = 1; o < 4; o <<= 1) {
            pa += __shfl_xor_sync(~0u, pa, o);
            pb += __shfl_xor_sync(~0u, pb, o);
        }
        if (t == 0) {
            red0[c32 * 64 + r1] = pa;
            red0[c32 * 64 + r2] = pb;
        }
        __syncthreads();
        if (tid < 64) {
            float P = red0[tid] + red0[64 + tid] + red0[128 + tid] + red0[192 + tid];
            out[base + tid] = 1.f / (1.f + expf(-P));
        }
    }
}

// ---------------------------------------------------------------------------
extern "C" void kernel_launch(void* const* d_in, const int* in_sizes, int n_in,
                              void* d_out, int out_size) {
    const float* em    = (const float*)d_in[0];
    const float* ed    = (const float*)d_in[1];
    const float* W_gcn = (const float*)d_in[2];
    const float* Wq_m  = (const float*)d_in[3];
    const float* Wk_m  = (const float*)d_in[4];
    const float* Wv_m  = (const float*)d_in[5];
    const float* Wq_d  = (const float*)d_in[6];
    const float* Wk_d  = (const float*)d_in[7];
    const float* Wv_d  = (const float*)d_in[8];
    const float* W1    = (const float*)d_in[9];
    const float* W2    = (const float*)d_in[10];
    float* out = (float*)d_out;

    const int B = in_sizes[0] / C;
    const int smem_bytes = U_TOT * 4;

    precompute_M_kernel<<<dim3(C, 2), C>>>(Wq_m, Wk_m, Wq_d, Wk_d);
    bake_kernel<<<dim3(8192 / 256, 6), 256>>>(W_gcn, Wv_m, Wv_d, W1);

    cudaFuncSetAttribute(fused_kernel,
                         cudaFuncAttributeMaxDynamicSharedMemorySize, smem_bytes);
    fused_kernel<<<B / 64, THREADS, smem_bytes>>>(em, ed, W2, out);
}

// round 12
// speedup vs baseline: 1.4080x; 1.1348x over previous
#include <cuda_runtime.h>
#include <cuda_bf16.h>
#include <cstdint>

#define C 128
#define LDW 132
#define WSTR 136
#define WPL (64 * WSTR)
#define THREADS 512
#define EPSF 1e-8f

__device__ float g_Mm[C * C];
__device__ float g_Md[C * C];
__device__ __align__(16) uint32_t g_BH[6][WPL];
__device__ __align__(16) uint32_t g_BL[6][WPL];

// ---- smem u32 layout ----
#define U_F0 16
#define U_F1 (U_F0 + 8448)
#define U_R2 (U_F1 + 8448)
#define U_R3 (U_R2 + 8448)
#define U_WH (U_R3 + 8448)
#define U_WL (U_WH + WPL)
#define U_RED (U_WL + WPL)   // red0[256], red1[256]
#define U_W0B (U_RED + 512)
#define U_W1B (U_W0B + 64)
#define U_AB (U_W1B + 64)
#define U_BB (U_AB + 64)
#define U_W2 (U_BB + 64)
#define U_TOT (U_W2 + 128)

__device__ __forceinline__ uint32_t s2u(const void* p) {
    uint32_t a;
    asm("{ .reg .u64 t; cvta.to.shared.u64 t, %1; cvt.u32.u64 %0, t; }" : "=r"(a) : "l"(p));
    return a;
}
#define MBAR_INIT(a, c) asm volatile("mbarrier.init.shared.b64 [%0], %1;" ::"r"(a), "r"(c) : "memory")
#define MBAR_EXPECT(a, b) \
    asm volatile("mbarrier.arrive.expect_tx.shared.b64 _, [%0], %1;" ::"r"(a), "r"(b) : "memory")
__device__ __forceinline__ void mbar_wait(uint32_t a, uint32_t par) {
    asm volatile(
        "{\n\t.reg .pred P;\n\tWL_%=:\n\t"
        "mbarrier.try_wait.parity.acquire.cta.shared::cta.b64 P, [%0], %1, 0x989680;\n\t"
        "@P bra.uni WD_%=;\n\tbra.uni WL_%=;\n\tWD_%=:\n\t}" ::"r"(a), "r"(par) : "memory");
}
__device__ __forceinline__ void bulk_g2s(uint32_t dst, const void* gsrc, uint32_t bytes,
                                         uint32_t mbar) {
    asm volatile(
        "{ .reg .u64 g; cvta.to.global.u64 g, %1;\n\t"
        "cp.async.bulk.shared::cluster.global.mbarrier::complete_tx::bytes [%0], [g], %2, [%3]; }"
        ::"r"(dst), "l"(gsrc), "r"(bytes), "r"(mbar) : "memory");
}

__device__ __forceinline__ void split_pack(float x0, float x1, uint32_t& h, uint32_t& l) {
    uint32_t u0 = __float_as_uint(x0), u1 = __float_as_uint(x1);
    h = __byte_perm(u0, u1, 0x7632);
    float l0 = x0 - __uint_as_float(u0 & 0xFFFF0000u);
    float l1 = x1 - __uint_as_float(u1 & 0xFFFF0000u);
    __nv_bfloat162 t = __floats2bfloat162_rn(l0, l1);
    l = *(uint32_t*)&t;
}
__device__ __forceinline__ uint2 pack2(float x, float y) {
    uint2 r;
    split_pack(x, y, r.x, r.y);
    return r;
}
__device__ __forceinline__ float2 unpack2(uint2 p) {
    float2 a = __bfloat1622float2(*(__nv_bfloat162*)&p.x);
    float2 b = __bfloat1622float2(*(__nv_bfloat162*)&p.y);
    return make_float2(a.x + b.x, a.y + b.y);
}
__device__ __forceinline__ void mma16816(float* d, const uint32_t* a, uint32_t b0, uint32_t b1) {
    asm volatile(
        "mma.sync.aligned.m16n8k16.row.col.f32.bf16.bf16.f32 "
        "{%0,%1,%2,%3}, {%4,%5,%6,%7}, {%8,%9}, {%0,%1,%2,%3};"
        : "+f"(d[0]), "+f"(d[1]), "+f"(d[2]), "+f"(d[3])
        : "r"(a[0]), "r"(a[1]), "r"(a[2]), "r"(a[3]), "r"(b0), "r"(b1));
}
#define MMA3(accn, bh0, bh1, bl0, bl1) \
    do {                               \
        mma16816(accn, ah, bh0, bh1);  \
        mma16816(accn, al, bh0, bh1);  \
        mma16816(accn, ah, bl0, bl1);  \
    } while (0)

// acc[nt][0..3]: rows (rb+g, rb+g+8), cols c32*32 + nt*8 + 2t (+1)
__device__ __forceinline__ void mma_block(const uint32_t* A, const uint32_t* WH,
                                          const uint32_t* WL, float acc[4][4], int rb, int c32,
                                          int g, int t) {
    const uint32_t* pa = A + (rb + g) * LDW + 2 * t;
    const uint32_t* pb = WH + t * WSTR + c32 * 32 + g * 4;
    const uint32_t* pc = WL + t * WSTR + c32 * 32 + g * 4;
#pragma unroll 2
    for (int k0 = 0; k0 < 8; k0++) {
        uint2 a0 = *(const uint2*)pa, a1 = *(const uint2*)(pa + 8 * LDW);
        uint2 a2 = *(const uint2*)(pa + 8), a3 = *(const uint2*)(pa + 8 * LDW + 8);
        uint4 bh0 = *(const uint4*)pb, bh1 = *(const uint4*)(pb + 4 * WSTR);
        uint4 bl0 = *(const uint4*)pc, bl1 = *(const uint4*)(pc + 4 * WSTR);
        uint32_t ah[4] = {a0.x, a1.x, a2.x, a3.x}, al[4] = {a0.y, a1.y, a2.y, a3.y};
        MMA3(acc[0], bh0.x, bh1.x, bl0.x, bl1.x);
        MMA3(acc[1], bh0.y, bh1.y, bl0.y, bl1.y);
        MMA3(acc[2], bh0.z, bh1.z, bl0.z, bl1.z);
        MMA3(acc[3], bh0.w, bh1.w, bl0.w, bl1.w);
        pa += 16;
        pb += 8 * WSTR;
        pc += 8 * WSTR;
    }
}
__device__ __forceinline__ void mma_block2(const uint32_t* A0, const uint32_t* A1,
                                           const uint32_t* WH, const uint32_t* WL,
                                           float acc0[4][4], float acc1[4][4], int rb, int c32,
                                           int g, int t) {
    const uint32_t* pa = A0 + (rb + g) * LDW + 2 * t;
    const uint32_t* pq = A1 + (rb + g) * LDW + 2 * t;
    const uint32_t* pb = WH + t * WSTR + c32 * 32 + g * 4;
    const uint32_t* pc = WL + t * WSTR + c32 * 32 + g * 4;
#pragma unroll 1
    for (int k0 = 0; k0 < 8; k0++) {
        uint4 bh0 = *(const uint4*)pb, bh1 = *(const uint4*)(pb + 4 * WSTR);
        uint4 bl0 = *(const uint4*)pc, bl1 = *(const uint4*)(pc + 4 * WSTR);
        {
            uint2 a0 = *(const uint2*)pa, a1 = *(const uint2*)(pa + 8 * LDW);
            uint2 a2 = *(const uint2*)(pa + 8), a3 = *(const uint2*)(pa + 8 * LDW + 8);
            uint32_t ah[4] = {a0.x, a1.x, a2.x, a3.x}, al[4] = {a0.y, a1.y, a2.y, a3.y};
            MMA3(acc0[0], bh0.x, bh1.x, bl0.x, bl1.x);
            MMA3(acc0[1], bh0.y, bh1.y, bl0.y, bl1.y);
            MMA3(acc0[2], bh0.z, bh1.z, bl0.z, bl1.z);
            MMA3(acc0[3], bh0.w, bh1.w, bl0.w, bl1.w);
        }
        {
            uint2 a0 = *(const uint2*)pq, a1 = *(const uint2*)(pq + 8 * LDW);
            uint2 a2 = *(const uint2*)(pq + 8), a3 = *(const uint2*)(pq + 8 * LDW + 8);
            uint32_t ah[4] = {a0.x, a1.x, a2.x, a3.x}, al[4] = {a0.y, a1.y, a2.y, a3.y};
            MMA3(acc1[0], bh0.x, bh1.x, bl0.x, bl1.x);
            MMA3(acc1[1], bh0.y, bh1.y, bl0.y, bl1.y);
            MMA3(acc1[2], bh0.z, bh1.z, bl0.z, bl1.z);
            MMA3(acc1[3], bh0.w, bh1.w, bl0.w, bl1.w);
        }
        pa += 16;
        pq += 16;
        pb += 8 * WSTR;
        pc += 8 * WSTR;
    }
}

// ---------------- prep ----------------
__global__ void precompute_M_kernel(const float* __restrict__ Wq_m, const float* __restrict__ Wk_m,
                                    const float* __restrict__ Wq_d, const float* __restrict__ Wk_d) {
    const float* Wq = blockIdx.y ? Wq_d : Wq_m;
    const float* Wk = blockIdx.y ? Wk_d : Wk_m;
    float* M = blockIdx.y ? g_Md : g_Mm;
    int i = blockIdx.x, t = threadIdx.x;
    __shared__ float qrow[C];
    qrow[t] = Wq[i * C + t];
    __syncthreads();
    const float* wkr = Wk + t * C;
    float a0 = 0.f, a1 = 0.f, a2 = 0.f, a3 = 0.f;
#pragma unroll 8
    for (int j = 0; j < C; j += 4) {
        a0 += qrow[j] * wkr[j];
        a1 += qrow[j + 1] * wkr[j + 1];
        a2 += qrow[j + 2] * wkr[j + 2];
        a3 += qrow[j + 3] * wkr[j + 3];
    }
    M[i * C + t] = ((a0 + a1) + (a2 + a3)) * 0.08838834764831845f;
}

__global__ void bake_kernel(const float* __restrict__ Wg, const float* __restrict__ Wvm,
                            const float* __restrict__ Wvd, const float* __restrict__ W1) {
    int w = blockIdx.y;
    const float* src = (w == 0) ? Wg : (w == 1) ? g_Mm : (w == 2) ? Wvm
                      : (w == 3) ? g_Md : (w == 4) ? Wvd : W1;
    int idx = blockIdx.x * blockDim.x + threadIdx.x;  // 0..8191
    int nt = idx & 3, g = (idx >> 2) & 7, c32 = (idx >> 5) & 3, k2 = idx >> 7;
    int n = c32 * 32 + nt * 8 + g;
    uint32_t h, l;
    split_pack(src[(2 * k2) * C + n], src[(2 * k2 + 1) * C + n], h, l);
    int dst = k2 * WSTR + (idx & 127);
    g_BH[w][dst] = h;
    g_BL[w][dst] = l;
}

// ---------------- fused ----------------
__global__ void __launch_bounds__(THREADS, 1)
fused_kernel(const float* __restrict__ em, const float* __restrict__ ed,
             const float* __restrict__ W2, float* __restrict__ out) {
    extern __shared__ uint32_t sm[];
    const uint32_t sb = s2u(sm);
    const uint32_t mb = sb;
    float* F0 = (float*)(sm + U_F0);
    float* F1 = (float*)(sm + U_F1);
    uint32_t* R2 = sm + U_R2;
    uint32_t* R3 = sm + U_R3;
    uint32_t* WH = sm + U_WH;
    uint32_t* WL = sm + U_WL;
    float* red0 = (float*)(sm + U_RED);
    float* red1 = red0 + 256;
    float* w0B = (float*)(sm + U_W0B);
    float* w1B = (float*)(sm + U_W1B);
    float* aB = (float*)(sm + U_AB);
    float* bB = (float*)(sm + U_BB);
    float* sW2 = (float*)(sm + U_W2);

    const int tid = threadIdx.x;
    const int w = tid >> 5, lane = tid & 31;
    const int g = lane >> 2, t = lane & 3;
    const int rb = (w & 3) * 16, c32 = w >> 2;
    const int r1 = rb + g, r2 = r1 + 8;
    const int cb = c32 * 32 + 2 * t;
    const int row4 = w * 4;
    const long base = (long)blockIdx.x * 64;

    if (tid == 0) {
        MBAR_INIT(mb, 1);
        MBAR_EXPECT(mb, 2 * WPL * 4);
        bulk_g2s(sb + U_WH * 4, &g_BH[0][0], WPL * 4, mb);
        bulk_g2s(sb + U_WL * 4, &g_BL[0][0], WPL * 4, mb);
    }
    {
        const float4* ge = (const float4*)(em + base * C);
        const float4* gd = (const float4*)(ed + base * C);
        for (int i = tid; i < 64 * 32; i += THREADS) {
            int r = i >> 5, c4 = i & 31;
            ((float4*)(F0 + r * LDW))[c4] = ge[i];
            ((float4*)(F1 + r * LDW))[c4] = gd[i];
        }
        if (tid < C) sW2[tid] = W2[tid];
    }
    __syncthreads();

    // adjacency scalars + pack em/ed
#pragma unroll
    for (int rr = 0; rr < 4; rr++) {
        int r = row4 + rr;
        const float* pe = F0 + r * LDW;
        const float* pd = F1 + r * LDW;
        float2 e0 = *(const float2*)(pe + 2 * lane), e1 = *(const float2*)(pe + 2 * lane + 64);
        float2 d0 = *(const float2*)(pd + 2 * lane), d1 = *(const float2*)(pd + 2 * lane + 64);
        float sa = fabsf(e0.x - d0.x) + fabsf(e0.y - d0.y) + fabsf(e1.x - d1.x) + fabsf(e1.y - d1.y);
        float q0 = e0.x * e0.x + e0.y * e0.y + e1.x * e1.x + e1.y * e1.y;
        float q1 = d0.x * d0.x + d0.y * d0.y + d1.x * d1.x + d1.y * d1.y;
        float dp = e0.x * d0.x + e0.y * d0.y + e1.x * d1.x + e1.y * d1.y;
#pragma unroll
        for (int o = 16; o; o >>= 1) {
            sa += __shfl_xor_sync(~0u, sa, o);
            q0 += __shfl_xor_sync(~0u, q0, o);
            q1 += __shfl_xor_sync(~0u, q1, o);
            dp += __shfl_xor_sync(~0u, dp, o);
        }
        if (lane == 0) {
            float m = sa;
            float cosv = dp / (sqrtf(q0 + EPSF) * sqrtf(q1 + EPSF));
            float cp = cosv > 0.f ? cosv : 0.01f * cosv;
            aB[r] = fminf(1.f / (1.f + cp), 1.f / (1.f + m));
            bB[r] = fminf(cp / (1.f + cp), m / (1.f + m));
        }
        *(uint2*)(R2 + r * LDW + 2 * lane) = pack2(e0.x, e0.y);
        *(uint2*)(R2 + r * LDW + 2 * lane + 64) = pack2(e1.x, e1.y);
        *(uint2*)(R3 + r * LDW + 2 * lane) = pack2(d0.x, d0.y);
        *(uint2*)(R3 + r * LDW + 2 * lane + 64) = pack2(d1.x, d1.y);
    }
    __syncthreads();

    auto prefetch = [&](int nw) {
        if (tid == 0) {
            MBAR_EXPECT(mb, 2 * WPL * 4);
            bulk_g2s(sb + U_WH * 4, &g_BH[nw][0], WPL * 4, mb);
            bulk_g2s(sb + U_WL * 4, &g_BL[nw][0], WPL * 4, mb);
        }
    };

    // ---------------- stage 0: GCN ----------------
    mbar_wait(mb, 0);
    {
        float a0[4][4] = {}, a1[4][4] = {};
        mma_block2(R2, R3, WH, WL, a0, a1, rb, c32, g, t);
        __syncthreads();
        prefetch(1);
        float aa1 = aB[r1], bb1 = bB[r1], aa2 = aB[r2], bb2 = bB[r2];
#pragma unroll
        for (int nt = 0; nt < 4; nt++) {
            int c = cb + nt * 8;
            float2 e1v = *(const float2*)(F0 + r1 * LDW + c);
            float2 e2v = *(const float2*)(F0 + r2 * LDW + c);
            float2 d1v = *(const float2*)(F1 + r1 * LDW + c);
            float2 d2v = *(const float2*)(F1 + r2 * LDW + c);
            *(uint2*)(R2 + r1 * LDW + c) = pack2(fmaxf(aa1 * a0[nt][0] + bb1 * a1[nt][0], 0.f) + e1v.x,
                                                 fmaxf(aa1 * a0[nt][1] + bb1 * a1[nt][1], 0.f) + e1v.y);
            *(uint2*)(R2 + r2 * LDW + c) = pack2(fmaxf(aa2 * a0[nt][2] + bb2 * a1[nt][2], 0.f) + e2v.x,
                                                 fmaxf(aa2 * a0[nt][3] + bb2 * a1[nt][3], 0.f) + e2v.y);
            *(uint2*)(R3 + r1 * LDW + c) = pack2(fmaxf(bb1 * a0[nt][0] + aa1 * a1[nt][0], 0.f) + d1v.x,
                                                 fmaxf(bb1 * a0[nt][1] + aa1 * a1[nt][1], 0.f) + d1v.y);
            *(uint2*)(R3 + r2 * LDW + c) = pack2(fmaxf(bb2 * a0[nt][2] + aa2 * a1[nt][2], 0.f) + d2v.x,
                                                 fmaxf(bb2 * a0[nt][3] + aa2 * a1[nt][3], 0.f) + d2v.y);
        }
    }
    __syncthreads();

    // T-stage: MMA + folded scores + softmax + in-register u-pack (u overwrites X)
    auto t_stage = [&](const float* F, uint32_t* X, int par, int nw) {
        mbar_wait(mb, par);
        float acc[4][4] = {};
        mma_block(X, WH, WL, acc, rb, c32, g, t);
        __syncthreads();
        prefetch(nw);
        float2 fA[4], fB[4], xA[4], xB[4];
        float s0a = 0.f, s1a = 0.f, s0b = 0.f, s1b = 0.f;
#pragma unroll
        for (int nt = 0; nt < 4; nt++) {
            int c = cb + nt * 8;
            fA[nt] = *(const float2*)(F + r1 * LDW + c);
            fB[nt] = *(const float2*)(F + r2 * LDW + c);
            xA[nt] = unpack2(*(const uint2*)(X + r1 * LDW + c));
            xB[nt] = unpack2(*(const uint2*)(X + r2 * LDW + c));
            s0a += acc[nt][0] * fA[nt].x + acc[nt][1] * fA[nt].y;
            s1a += acc[nt][0] * xA[nt].x + acc[nt][1] * xA[nt].y;
            s0b += acc[nt][2] * fB[nt].x + acc[nt][3] * fB[nt].y;
            s1b += acc[nt][2] * xB[nt].x + acc[nt][3] * xB[nt].y;
        }
#pragma unroll
        for (int o = 1; o < 4; o <<= 1) {
            s0a += __shfl_xor_sync(~0u, s0a, o);
            s1a += __shfl_xor_sync(~0u, s1a, o);
            s0b += __shfl_xor_sync(~0u, s0b, o);
            s1b += __shfl_xor_sync(~0u, s1b, o);
        }
        if (t == 0) {
            red0[c32 * 64 + r1] = s0a;
            red1[c32 * 64 + r1] = s1a;
            red0[c32 * 64 + r2] = s0b;
            red1[c32 * 64 + r2] = s1b;
        }
        __syncthreads();
        if (tid < 64) {
            float S0 = red0[tid] + red0[64 + tid] + red0[128 + tid] + red0[192 + tid];
            float S1 = red1[tid] + red1[64 + tid] + red1[128 + tid] + red1[192 + tid];
            float mx = fmaxf(S0, S1);
            float e0 = expf(S0 - mx), e1 = expf(S1 - mx);
            float inv = 1.f / (e0 + e1);
            w0B[tid] = e0 * inv;
            w1B[tid] = e1 * inv;
        }
        __syncthreads();
        float w01 = w0B[r1], w11 = w1B[r1], w02 = w0B[r2], w12 = w1B[r2];
#pragma unroll
        for (int nt = 0; nt < 4; nt++) {
            int c = cb + nt * 8;
            *(uint2*)(X + r1 * LDW + c) =
                pack2(w01 * fA[nt].x + w11 * xA[nt].x, w01 * fA[nt].y + w11 * xA[nt].y);
            *(uint2*)(X + r2 * LDW + c) =
                pack2(w02 * fB[nt].x + w12 * xB[nt].x, w02 * fB[nt].y + w12 * xB[nt].y);
        }
        __syncthreads();
    };

    // ---------------- m branch ----------------
    t_stage(F0, R2, 1, 2);  // u_m -> R2
    float mla[4][4] = {};
    mbar_wait(mb, 0);       // Wvm
    mma_block(R2, WH, WL, mla, rb, c32, g, t);  // mLA stays in registers
    __syncthreads();
    prefetch(3);

    // ---------------- d branch ----------------
    t_stage(F1, R3, 1, 4);  // u_d -> R3
    mbar_wait(mb, 0);       // Wvd
    {
        float acc[4][4] = {};
        mma_block(R3, WH, WL, acc, rb, c32, g, t);
        __syncthreads();
        prefetch(5);
#pragma unroll
        for (int nt = 0; nt < 4; nt++) {  // ne = mLA(regs) * dLA(regs) -> R2 packed
            int c = cb + nt * 8;
            *(uint2*)(R2 + r1 * LDW + c) = pack2(mla[nt][0] * acc[nt][0], mla[nt][1] * acc[nt][1]);
            *(uint2*)(R2 + r2 * LDW + c) = pack2(mla[nt][2] * acc[nt][2], mla[nt][3] * acc[nt][3]);
        }
    }
    __syncthreads();

    // ---------------- head ----------------
    mbar_wait(mb, 1);  // W1
    {
        float acc[4][4] = {};
        mma_block(R2, WH, WL, acc, rb, c32, g, t);
        float pa = 0.f, pb = 0.f;
#pragma unroll
        for (int nt = 0; nt < 4; nt++) {
            int c = cb + nt * 8;
            float2 wv = *(const float2*)(sW2 + c);
            pa += fmaxf(acc[nt][0], 0.f) * wv.x + fmaxf(acc[nt][1], 0.f) * wv.y;
            pb += fmaxf(acc[nt][2], 0.f) * wv.x + fmaxf(acc[nt][3], 0.f) * wv.y;
        }
#pragma unroll
        for (int o = 1; o < 4; o <<= 1) {
            pa += __shfl_xor_sync(~0u, pa, o);
            pb += __shfl_xor_sync(~0u, pb, o);
        }
        __syncthreads();
        if (t == 0) {
            red0[c32 * 64 + r1] = pa;
            red0[c32 * 64 + r2] = pb;
        }
        __syncthreads();
        if (tid < 64) {
            float P = red0[tid] + red0[64 + tid] + red0[128 + tid] + red0[192 + tid];
            out[base + tid] = 1.f / (1.f + expf(-P));
        }
    }
}

// ---------------------------------------------------------------------------
extern "C" void kernel_launch(void* const* d_in, const int* in_sizes, int n_in,
                              void* d_out, int out_size) {
    const float* em    = (const float*)d_in[0];
    const float* ed    = (const float*)d_in[1];
    const float* W_gcn = (const float*)d_in[2];
    const float* Wq_m  = (const float*)d_in[3];
    const float* Wk_m  = (const float*)d_in[4];
    const float* Wv_m  = (const float*)d_in[5];
    const float* Wq_d  = (const float*)d_in[6];
    const float* Wk_d  = (const float*)d_in[7];
    const float* Wv_d  = (const float*)d_in[8];
    const float* W1    = (const float*)d_in[9];
    const float* W2    = (const float*)d_in[10];
    float* out = (float*)d_out;

    const int B = in_sizes[0] / C;
    const int smem_bytes = U_TOT * 4;

    precompute_M_kernel<<<dim3(C, 2), C>>>(Wq_m, Wk_m, Wq_d, Wk_d);
    bake_kernel<<<dim3(8192 / 256, 6), 256>>>(W_gcn, Wv_m, Wv_d, W1);

    cudaFuncSetAttribute(fused_kernel,
                         cudaFuncAttributeMaxDynamicSharedMemorySize, smem_bytes);
    fused_kernel<<<B / 64, THREADS, smem_bytes>>>(em, ed, W2, out);
}

// round 13
// speedup vs baseline: 1.4654x; 1.0407x over previous
#include <cuda_runtime.h>
#include <cuda_bf16.h>
#include <cstdint>

#define C 128
#define LDW 132
#define WSTR 136
#define WPL (64 * WSTR)
#define THREADS 512
#define EPSF 1e-8f

__device__ float g_Mm[C * C];
__device__ float g_Md[C * C];
// bake order: 0 Wgcn, 1 Mm, 2 Wvm, 3 Md, 4 Wvd, 5 W1
__device__ __align__(16) uint32_t g_BH[6][WPL];
__device__ __align__(16) uint32_t g_BL[6][WPL];

// ---- smem u32 layout ----
#define U_R2 16
#define U_R3 (U_R2 + 8448)
#define U_WA (U_R3 + 8448)        // slot A: [WH | WL], 2*WPL
#define U_WB (U_WA + 2 * WPL)     // slot B
#define U_RED (U_WB + 2 * WPL)    // 4 x 256 floats
#define U_WS (U_RED + 1024)       // 4 x 64 floats: w0m,w1m,w0d,w1d
#define U_AB (U_WS + 256)
#define U_BB (U_AB + 64)
#define U_W2 (U_BB + 64)
#define U_TOT (U_W2 + 128)        // 53264 u32 = 213,056 B

__device__ __forceinline__ uint32_t s2u(const void* p) {
    uint32_t a;
    asm("{ .reg .u64 t; cvta.to.shared.u64 t, %1; cvt.u32.u64 %0, t; }" : "=r"(a) : "l"(p));
    return a;
}
#define MBAR_INIT(a, c) asm volatile("mbarrier.init.shared.b64 [%0], %1;" ::"r"(a), "r"(c) : "memory")
#define MBAR_EXPECT(a, b) \
    asm volatile("mbarrier.arrive.expect_tx.shared.b64 _, [%0], %1;" ::"r"(a), "r"(b) : "memory")
__device__ __forceinline__ void mbar_wait(uint32_t a, uint32_t par) {
    asm volatile(
        "{\n\t.reg .pred P;\n\tWL_%=:\n\t"
        "mbarrier.try_wait.parity.acquire.cta.shared::cta.b64 P, [%0], %1, 0x989680;\n\t"
        "@P bra.uni WD_%=;\n\tbra.uni WL_%=;\n\tWD_%=:\n\t}" ::"r"(a), "r"(par) : "memory");
}
__device__ __forceinline__ void bulk_g2s(uint32_t dst, const void* gsrc, uint32_t bytes,
                                         uint32_t mbar) {
    asm volatile(
        "{ .reg .u64 g; cvta.to.global.u64 g, %1;\n\t"
        "cp.async.bulk.shared::cluster.global.mbarrier::complete_tx::bytes [%0], [g], %2, [%3]; }"
        ::"r"(dst), "l"(gsrc), "r"(bytes), "r"(mbar) : "memory");
}

__device__ __forceinline__ void split_pack(float x0, float x1, uint32_t& h, uint32_t& l) {
    uint32_t u0 = __float_as_uint(x0), u1 = __float_as_uint(x1);
    h = __byte_perm(u0, u1, 0x7632);
    float l0 = x0 - __uint_as_float(u0 & 0xFFFF0000u);
    float l1 = x1 - __uint_as_float(u1 & 0xFFFF0000u);
    __nv_bfloat162 t = __floats2bfloat162_rn(l0, l1);
    l = *(uint32_t*)&t;
}
__device__ __forceinline__ uint2 pack2(float x, float y) {
    uint2 r;
    split_pack(x, y, r.x, r.y);
    return r;
}
__device__ __forceinline__ float2 unpack2(uint2 p) {
    float2 a = __bfloat1622float2(*(__nv_bfloat162*)&p.x);
    float2 b = __bfloat1622float2(*(__nv_bfloat162*)&p.y);
    return make_float2(a.x + b.x, a.y + b.y);
}
__device__ __forceinline__ void mma16816(float* d, const uint32_t* a, uint32_t b0, uint32_t b1) {
    asm volatile(
        "mma.sync.aligned.m16n8k16.row.col.f32.bf16.bf16.f32 "
        "{%0,%1,%2,%3}, {%4,%5,%6,%7}, {%8,%9}, {%0,%1,%2,%3};"
        : "+f"(d[0]), "+f"(d[1]), "+f"(d[2]), "+f"(d[3])
        : "r"(a[0]), "r"(a[1]), "r"(a[2]), "r"(a[3]), "r"(b0), "r"(b1));
}
#define MMA3(accn, bh0, bh1, bl0, bl1) \
    do {                               \
        mma16816(accn, ah, bh0, bh1);  \
        mma16816(accn, al, bh0, bh1);  \
        mma16816(accn, ah, bl0, bl1);  \
    } while (0)

// acc[nt][0..3]: rows (rb+g, rb+g+8), cols c32*32 + nt*8 + 2t (+1). W = slot base (WH | WL)
__device__ __forceinline__ void mma_block(const uint32_t* A, const uint32_t* W, float acc[4][4],
                                          int rb, int c32, int g, int t) {
    const uint32_t* pa = A + (rb + g) * LDW + 2 * t;
    const uint32_t* pb = W + t * WSTR + c32 * 32 + g * 4;
    const uint32_t* pc = pb + WPL;
#pragma unroll 2
    for (int k0 = 0; k0 < 8; k0++) {
        uint2 a0 = *(const uint2*)pa, a1 = *(const uint2*)(pa + 8 * LDW);
        uint2 a2 = *(const uint2*)(pa + 8), a3 = *(const uint2*)(pa + 8 * LDW + 8);
        uint4 bh0 = *(const uint4*)pb, bh1 = *(const uint4*)(pb + 4 * WSTR);
        uint4 bl0 = *(const uint4*)pc, bl1 = *(const uint4*)(pc + 4 * WSTR);
        uint32_t ah[4] = {a0.x, a1.x, a2.x, a3.x}, al[4] = {a0.y, a1.y, a2.y, a3.y};
        MMA3(acc[0], bh0.x, bh1.x, bl0.x, bl1.x);
        MMA3(acc[1], bh0.y, bh1.y, bl0.y, bl1.y);
        MMA3(acc[2], bh0.z, bh1.z, bl0.z, bl1.z);
        MMA3(acc[3], bh0.w, bh1.w, bl0.w, bl1.w);
        pa += 16;
        pb += 8 * WSTR;
        pc += 8 * WSTR;
    }
}
__device__ __forceinline__ void mma_block2(const uint32_t* A0, const uint32_t* A1,
                                           const uint32_t* W, float acc0[4][4], float acc1[4][4],
                                           int rb, int c32, int g, int t) {
    const uint32_t* pa = A0 + (rb + g) * LDW + 2 * t;
    const uint32_t* pq = A1 + (rb + g) * LDW + 2 * t;
    const uint32_t* pb = W + t * WSTR + c32 * 32 + g * 4;
    const uint32_t* pc = pb + WPL;
#pragma unroll 1
    for (int k0 = 0; k0 < 8; k0++) {
        uint4 bh0 = *(const uint4*)pb, bh1 = *(const uint4*)(pb + 4 * WSTR);
        uint4 bl0 = *(const uint4*)pc, bl1 = *(const uint4*)(pc + 4 * WSTR);
        {
            uint2 a0 = *(const uint2*)pa, a1 = *(const uint2*)(pa + 8 * LDW);
            uint2 a2 = *(const uint2*)(pa + 8), a3 = *(const uint2*)(pa + 8 * LDW + 8);
            uint32_t ah[4] = {a0.x, a1.x, a2.x, a3.x}, al[4] = {a0.y, a1.y, a2.y, a3.y};
            MMA3(acc0[0], bh0.x, bh1.x, bl0.x, bl1.x);
            MMA3(acc0[1], bh0.y, bh1.y, bl0.y, bl1.y);
            MMA3(acc0[2], bh0.z, bh1.z, bl0.z, bl1.z);
            MMA3(acc0[3], bh0.w, bh1.w, bl0.w, bl1.w);
        }
        {
            uint2 a0 = *(const uint2*)pq, a1 = *(const uint2*)(pq + 8 * LDW);
            uint2 a2 = *(const uint2*)(pq + 8), a3 = *(const uint2*)(pq + 8 * LDW + 8);
            uint32_t ah[4] = {a0.x, a1.x, a2.x, a3.x}, al[4] = {a0.y, a1.y, a2.y, a3.y};
            MMA3(acc1[0], bh0.x, bh1.x, bl0.x, bl1.x);
            MMA3(acc1[1], bh0.y, bh1.y, bl0.y, bl1.y);
            MMA3(acc1[2], bh0.z, bh1.z, bl0.z, bl1.z);
            MMA3(acc1[3], bh0.w, bh1.w, bl0.w, bl1.w);
        }
        pa += 16;
        pq += 16;
        pb += 8 * WSTR;
        pc += 8 * WSTR;
    }
}

// ---------------- prep ----------------
__global__ void precompute_M_kernel(const float* __restrict__ Wq_m, const float* __restrict__ Wk_m,
                                    const float* __restrict__ Wq_d, const float* __restrict__ Wk_d) {
    const float* Wq = blockIdx.y ? Wq_d : Wq_m;
    const float* Wk = blockIdx.y ? Wk_d : Wk_m;
    float* M = blockIdx.y ? g_Md : g_Mm;
    int i = blockIdx.x, t = threadIdx.x;
    __shared__ float qrow[C];
    qrow[t] = Wq[i * C + t];
    __syncthreads();
    const float* wkr = Wk + t * C;
    float a0 = 0.f, a1 = 0.f, a2 = 0.f, a3 = 0.f;
#pragma unroll 8
    for (int j = 0; j < C; j += 4) {
        a0 += qrow[j] * wkr[j];
        a1 += qrow[j + 1] * wkr[j + 1];
        a2 += qrow[j + 2] * wkr[j + 2];
        a3 += qrow[j + 3] * wkr[j + 3];
    }
    M[i * C + t] = ((a0 + a1) + (a2 + a3)) * 0.08838834764831845f;
}

__global__ void bake_kernel(const float* __restrict__ Wg, const float* __restrict__ Wvm,
                            const float* __restrict__ Wvd, const float* __restrict__ W1) {
    int w = blockIdx.y;
    const float* src = (w == 0) ? Wg : (w == 1) ? g_Mm : (w == 2) ? Wvm
                      : (w == 3) ? g_Md : (w == 4) ? Wvd : W1;
    int idx = blockIdx.x * blockDim.x + threadIdx.x;  // 0..8191
    int nt = idx & 3, g = (idx >> 2) & 7, c32 = (idx >> 5) & 3, k2 = idx >> 7;
    int n = c32 * 32 + nt * 8 + g;
    uint32_t h, l;
    split_pack(src[(2 * k2) * C + n], src[(2 * k2 + 1) * C + n], h, l);
    int dst = k2 * WSTR + (idx & 127);
    g_BH[w][dst] = h;
    g_BL[w][dst] = l;
}

// ---------------- fused ----------------
__global__ void __launch_bounds__(THREADS, 1)
fused_kernel(const float* __restrict__ em, const float* __restrict__ ed,
             const float* __restrict__ W2, float* __restrict__ out) {
    extern __shared__ uint32_t sm[];
    const uint32_t sb = s2u(sm);
    const uint32_t mbA = sb, mbB = sb + 8;
    uint32_t* R2 = sm + U_R2;
    uint32_t* R3 = sm + U_R3;
    uint32_t* WA = sm + U_WA;
    uint32_t* WB = sm + U_WB;
    float* red = (float*)(sm + U_RED);  // [4][256]
    float* wS = (float*)(sm + U_WS);    // [4][64]: w0m,w1m,w0d,w1d
    float* aB = (float*)(sm + U_AB);
    float* bB = (float*)(sm + U_BB);
    float* sW2 = (float*)(sm + U_W2);

    const int tid = threadIdx.x;
    const int w = tid >> 5, lane = tid & 31;
    const int g = lane >> 2, t = lane & 3;
    const int rb = (w & 3) * 16, c32 = w >> 2;
    const int r1 = rb + g, r2 = r1 + 8;
    const int cb = c32 * 32 + 2 * t;
    const int row4 = w * 4;
    const long base = (long)blockIdx.x * 64;

    auto copy_slot = [&](uint32_t mbar, uint32_t slot_u32, int wi) {
        MBAR_EXPECT(mbar, 2u * WPL * 4);
        bulk_g2s(sb + slot_u32 * 4, &g_BH[wi][0], WPL * 4, mbar);
        bulk_g2s(sb + (slot_u32 + WPL) * 4, &g_BL[wi][0], WPL * 4, mbar);
    };

    if (tid == 0) {
        MBAR_INIT(mbA, 1);
        MBAR_INIT(mbB, 1);
        copy_slot(mbA, U_WA, 0);  // Wgcn -> A
        copy_slot(mbB, U_WB, 1);  // Mm   -> B
    }
    if (tid < C) sW2[tid] = W2[tid];

    // adjacency scalars + pack em/ed from GLOBAL (warp owns rows row4..row4+3)
#pragma unroll
    for (int rr = 0; rr < 4; rr++) {
        int r = row4 + rr;
        const float* pe = em + (base + r) * C;
        const float* pd = ed + (base + r) * C;
        float2 e0 = *(const float2*)(pe + 2 * lane), e1 = *(const float2*)(pe + 2 * lane + 64);
        float2 d0 = *(const float2*)(pd + 2 * lane), d1 = *(const float2*)(pd + 2 * lane + 64);
        float sa = fabsf(e0.x - d0.x) + fabsf(e0.y - d0.y) + fabsf(e1.x - d1.x) + fabsf(e1.y - d1.y);
        float q0 = e0.x * e0.x + e0.y * e0.y + e1.x * e1.x + e1.y * e1.y;
        float q1 = d0.x * d0.x + d0.y * d0.y + d1.x * d1.x + d1.y * d1.y;
        float dp = e0.x * d0.x + e0.y * d0.y + e1.x * d1.x + e1.y * d1.y;
#pragma unroll
        for (int o = 16; o; o >>= 1) {
            sa += __shfl_xor_sync(~0u, sa, o);
            q0 += __shfl_xor_sync(~0u, q0, o);
            q1 += __shfl_xor_sync(~0u, q1, o);
            dp += __shfl_xor_sync(~0u, dp, o);
        }
        if (lane == 0) {
            float m = sa;
            float cosv = dp / (sqrtf(q0 + EPSF) * sqrtf(q1 + EPSF));
            float cp = cosv > 0.f ? cosv : 0.01f * cosv;
            aB[r] = fminf(1.f / (1.f + cp), 1.f / (1.f + m));
            bB[r] = fminf(cp / (1.f + cp), m / (1.f + m));
        }
        *(uint2*)(R2 + r * LDW + 2 * lane) = pack2(e0.x, e0.y);
        *(uint2*)(R2 + r * LDW + 2 * lane + 64) = pack2(e1.x, e1.y);
        *(uint2*)(R3 + r * LDW + 2 * lane) = pack2(d0.x, d0.y);
        *(uint2*)(R3 + r * LDW + 2 * lane + 64) = pack2(d1.x, d1.y);
    }
    __syncthreads();

    // ---------------- GCN (slot A: Wgcn) ----------------
    mbar_wait(mbA, 0);
    {
        float a0[4][4] = {}, a1[4][4] = {};
        mma_block2(R2, R3, WA, a0, a1, rb, c32, g, t);
        __syncthreads();                       // Wgcn + em/ed packs consumed
        if (tid == 0) copy_slot(mbA, U_WA, 3);  // Md -> A
        float aa1 = aB[r1], bb1 = bB[r1], aa2 = aB[r2], bb2 = bB[r2];
#pragma unroll
        for (int nt = 0; nt < 4; nt++) {
            int c = cb + nt * 8;
            float2 e1v = *(const float2*)(em + (base + r1) * C + c);
            float2 e2v = *(const float2*)(em + (base + r2) * C + c);
            float2 d1v = *(const float2*)(ed + (base + r1) * C + c);
            float2 d2v = *(const float2*)(ed + (base + r2) * C + c);
            *(uint2*)(R2 + r1 * LDW + c) = pack2(fmaxf(aa1 * a0[nt][0] + bb1 * a1[nt][0], 0.f) + e1v.x,
                                                 fmaxf(aa1 * a0[nt][1] + bb1 * a1[nt][1], 0.f) + e1v.y);
            *(uint2*)(R2 + r2 * LDW + c) = pack2(fmaxf(aa2 * a0[nt][2] + bb2 * a1[nt][2], 0.f) + e2v.x,
                                                 fmaxf(aa2 * a0[nt][3] + bb2 * a1[nt][3], 0.f) + e2v.y);
            *(uint2*)(R3 + r1 * LDW + c) = pack2(fmaxf(bb1 * a0[nt][0] + aa1 * a1[nt][0], 0.f) + d1v.x,
                                                 fmaxf(bb1 * a0[nt][1] + aa1 * a1[nt][1], 0.f) + d1v.y);
            *(uint2*)(R3 + r2 * LDW + c) = pack2(fmaxf(bb2 * a0[nt][2] + aa2 * a1[nt][2], 0.f) + d2v.x,
                                                 fmaxf(bb2 * a0[nt][3] + aa2 * a1[nt][3], 0.f) + d2v.y);
        }
    }
    __syncthreads();

    // ---------------- T stage: T_m (slot B: Mm), T_d (slot A: Md) ----------------
    float2 xAm[4], xBm[4], xAd[4], xBd[4];
    {
        float accm[4][4] = {}, accd[4][4] = {};
        mbar_wait(mbB, 0);
        mma_block(R2, WB, accm, rb, c32, g, t);
        mbar_wait(mbA, 1);
        mma_block(R3, WA, accd, rb, c32, g, t);
        __syncthreads();                        // Mm, Md, x packs consumed
        if (tid == 0) {
            copy_slot(mbB, U_WB, 2);  // Wvm -> B
            copy_slot(mbA, U_WA, 4);  // Wvd -> A
        }
        // scores, both branches
        float s0a = 0.f, s1a = 0.f, s0b = 0.f, s1b = 0.f;
        float u0a = 0.f, u1a = 0.f, u0b = 0.f, u1b = 0.f;
#pragma unroll
        for (int nt = 0; nt < 4; nt++) {
            int c = cb + nt * 8;
            float2 f1 = *(const float2*)(em + (base + r1) * C + c);
            float2 f2 = *(const float2*)(em + (base + r2) * C + c);
            float2 h1 = *(const float2*)(ed + (base + r1) * C + c);
            float2 h2 = *(const float2*)(ed + (base + r2) * C + c);
            xAm[nt] = unpack2(*(const uint2*)(R2 + r1 * LDW + c));
            xBm[nt] = unpack2(*(const uint2*)(R2 + r2 * LDW + c));
            xAd[nt] = unpack2(*(const uint2*)(R3 + r1 * LDW + c));
            xBd[nt] = unpack2(*(const uint2*)(R3 + r2 * LDW + c));
            s0a += accm[nt][0] * f1.x + accm[nt][1] * f1.y;
            s1a += accm[nt][0] * xAm[nt].x + accm[nt][1] * xAm[nt].y;
            s0b += accm[nt][2] * f2.x + accm[nt][3] * f2.y;
            s1b += accm[nt][2] * xBm[nt].x + accm[nt][3] * xBm[nt].y;
            u0a += accd[nt][0] * h1.x + accd[nt][1] * h1.y;
            u1a += accd[nt][0] * xAd[nt].x + accd[nt][1] * xAd[nt].y;
            u0b += accd[nt][2] * h2.x + accd[nt][3] * h2.y;
            u1b += accd[nt][2] * xBd[nt].x + accd[nt][3] * xBd[nt].y;
        }
#pragma unroll
        for (int o = 1; o < 4; o <<= 1) {
            s0a += __shfl_xor_sync(~0u, s0a, o);
            s1a += __shfl_xor_sync(~0u, s1a, o);
            s0b += __shfl_xor_sync(~0u, s0b, o);
            s1b += __shfl_xor_sync(~0u, s1b, o);
            u0a += __shfl_xor_sync(~0u, u0a, o);
            u1a += __shfl_xor_sync(~0u, u1a, o);
            u0b += __shfl_xor_sync(~0u, u0b, o);
            u1b += __shfl_xor_sync(~0u, u1b, o);
        }
        if (t == 0) {
            red[0 * 256 + c32 * 64 + r1] = s0a;
            red[1 * 256 + c32 * 64 + r1] = s1a;
            red[0 * 256 + c32 * 64 + r2] = s0b;
            red[1 * 256 + c32 * 64 + r2] = s1b;
            red[2 * 256 + c32 * 64 + r1] = u0a;
            red[3 * 256 + c32 * 64 + r1] = u1a;
            red[2 * 256 + c32 * 64 + r2] = u0b;
            red[3 * 256 + c32 * 64 + r2] = u1b;
        }
    }
    __syncthreads();
    if (tid < 128) {  // softmax for both branches: b = tid>>6, r = tid&63
        int b = tid >> 6, r = tid & 63;
        const float* p0 = red + (2 * b) * 256 + r;
        const float* p1 = red + (2 * b + 1) * 256 + r;
        float S0 = p0[0] + p0[64] + p0[128] + p0[192];
        float S1 = p1[0] + p1[64] + p1[128] + p1[192];
        float mx = fmaxf(S0, S1);
        float e0 = expf(S0 - mx), e1 = expf(S1 - mx);
        float inv = 1.f / (e0 + e1);
        wS[(2 * b) * 64 + r] = e0 * inv;
        wS[(2 * b + 1) * 64 + r] = e1 * inv;
    }
    __syncthreads();
    {  // u-pack both branches (f reloaded from global; x held in regs)
        float w0m1 = wS[r1], w1m1 = wS[64 + r1], w0m2 = wS[r2], w1m2 = wS[64 + r2];
        float w0d1 = wS[128 + r1], w1d1 = wS[192 + r1], w0d2 = wS[128 + r2], w1d2 = wS[192 + r2];
#pragma unroll
        for (int nt = 0; nt < 4; nt++) {
            int c = cb + nt * 8;
            float2 f1 = *(const float2*)(em + (base + r1) * C + c);
            float2 f2 = *(const float2*)(em + (base + r2) * C + c);
            float2 h1 = *(const float2*)(ed + (base + r1) * C + c);
            float2 h2 = *(const float2*)(ed + (base + r2) * C + c);
            *(uint2*)(R2 + r1 * LDW + c) =
                pack2(w0m1 * f1.x + w1m1 * xAm[nt].x, w0m1 * f1.y + w1m1 * xAm[nt].y);
            *(uint2*)(R2 + r2 * LDW + c) =
                pack2(w0m2 * f2.x + w1m2 * xBm[nt].x, w0m2 * f2.y + w1m2 * xBm[nt].y);
            *(uint2*)(R3 + r1 * LDW + c) =
                pack2(w0d1 * h1.x + w1d1 * xAd[nt].x, w0d1 * h1.y + w1d1 * xAd[nt].y);
            *(uint2*)(R3 + r2 * LDW + c) =
                pack2(w0d2 * h2.x + w1d2 * xBd[nt].x, w0d2 * h2.y + w1d2 * xBd[nt].y);
        }
    }
    __syncthreads();

    // ---------------- V stage: mLA (slot B: Wvm), dLA (slot A: Wvd) ----------------
    {
        float mla[4][4] = {}, dla[4][4] = {};
        mbar_wait(mbB, 1);
        mma_block(R2, WB, mla, rb, c32, g, t);
        mbar_wait(mbA, 0);  // 3rd completion on A
        mma_block(R3, WA, dla, rb, c32, g, t);
        __syncthreads();
        if (tid == 0) copy_slot(mbB, U_WB, 5);  // W1 -> B
#pragma unroll
        for (int nt = 0; nt < 4; nt++) {  // ne = mLA*dLA -> R2 packed
            int c = cb + nt * 8;
            *(uint2*)(R2 + r1 * LDW + c) = pack2(mla[nt][0] * dla[nt][0], mla[nt][1] * dla[nt][1]);
            *(uint2*)(R2 + r2 * LDW + c) = pack2(mla[nt][2] * dla[nt][2], mla[nt][3] * dla[nt][3]);
        }
    }
    __syncthreads();

    // ---------------- head (slot B: W1) ----------------
    mbar_wait(mbB, 0);  // 3rd completion on B
    {
        float acc[4][4] = {};
        mma_block(R2, WB, acc, rb, c32, g, t);
        float pa = 0.f, pb = 0.f;
#pragma unroll
        for (int nt = 0; nt < 4; nt++) {
            int c = cb + nt * 8;
            float2 wv = *(const float2*)(sW2 + c);
            pa += fmaxf(acc[nt][0], 0.f) * wv.x + fmaxf(acc[nt][1], 0.f) * wv.y;
            pb += fmaxf(acc[nt][2], 0.f) * wv.x + fmaxf(acc[nt][3], 0.f) * wv.y;
        }
#pragma unroll
        for (int o = 1; o < 4; o <<= 1) {
            pa += __shfl_xor_sync(~0u, pa, o);
            pb += __shfl_xor_sync(~0u, pb, o);
        }
        __syncthreads();
        if (t == 0) {
            red[c32 * 64 + r1] = pa;
            red[c32 * 64 + r2] = pb;
        }
        __syncthreads();
        if (tid < 64) {
            float P = red[tid] + red[64 + tid] + red[128 + tid] + red[192 + tid];
            out[base + tid] = 1.f / (1.f + expf(-P));
        }
    }
}

// ---------------------------------------------------------------------------
extern "C" void kernel_launch(void* const* d_in, const int* in_sizes, int n_in,
                              void* d_out, int out_size) {
    const float* em    = (const float*)d_in[0];
    const float* ed    = (const float*)d_in[1];
    const float* W_gcn = (const float*)d_in[2];
    const float* Wq_m  = (const float*)d_in[3];
    const float* Wk_m  = (const float*)d_in[4];
    const float* Wv_m  = (const float*)d_in[5];
    const float* Wq_d  = (const float*)d_in[6];
    const float* Wk_d  = (const float*)d_in[7];
    const float* Wv_d  = (const float*)d_in[8];
    const float* W1    = (const float*)d_in[9];
    const float* W2    = (const float*)d_in[10];
    float* out = (float*)d_out;

    const int B = in_sizes[0] / C;
    const int smem_bytes = U_TOT * 4;  // 213,056

    precompute_M_kernel<<<dim3(C, 2), C>>>(Wq_m, Wk_m, Wq_d, Wk_d);
    bake_kernel<<<dim3(8192 / 256, 6), 256>>>(W_gcn, Wv_m, Wv_d, W1);

    cudaFuncSetAttribute(fused_kernel,
                         cudaFuncAttributeMaxDynamicSharedMemorySize, smem_bytes);
    fused_kernel<<<B / 64, THREADS, smem_bytes>>>(em, ed, W2, out);
}